// round 3
// baseline (speedup 1.0000x reference)
#include <cuda_runtime.h>
#include <cuda_bf16.h>

// Problem constants
#define Bc 8
#define Cc 5
#define Hc 64
#define Wc 2048
#define Nc 1048576
#define Dc 64
#define Fc 4
#define HWc (Hc * Wc)                  // 131072

// Output section offsets (float32 elements, reference tuple order)
#define OFF_SCAN   0LL
#define OFF_COORD  5242880LL           // B*C*H*W
#define OFF_LABEL  11534336LL          // + 2N*3
#define OFF_EMBED  12582912LL          // + B*H*W
#define OFF_VALID  146800640LL         // + 2N*D

// Grid split: A (scan/label) blocks first, then B (points) blocks.
#define A_TOTAL   (Bc * Hc * (Wc / 4))     // 131072 threads
#define A_BLOCKS  ((A_TOTAL + 255) / 256)  // 512
#define B_BLOCKS  (Nc / 64)                // 16384 (64 points / 256-thr block, 2 per group)

__device__ __forceinline__ bool box_eval(
    const int* s_h1, const int* s_h2, const int* s_w1, const int* s_w2,
    int b, int h, int w)
{
    bool r = false;
#pragma unroll
    for (int f = 0; f < Fc; f++) {
        int i = b * Fc + f;
        r |= (h >= s_h1[i]) & (h < s_h2[i]) & (w >= s_w1[i]) & (w < s_w2[i]);
    }
    return r;
}

__global__ __launch_bounds__(256) void range_mix_fused_kernel(
    const float* __restrict__ scan,
    const int*   __restrict__ pc,
    const float* __restrict__ embed,
    const int*   __restrict__ label,
    const int*   __restrict__ u,
    const int*   __restrict__ bbw1, const int* __restrict__ bbw2,
    const int*   __restrict__ bbh1, const int* __restrict__ bbh2,
    float*       __restrict__ out)
{
    const int tid = threadIdx.x;

    if (blockIdx.x < A_BLOCKS) {
        // ----------------- Part A: mix_range_scan + mix_pred_label -----------------
        int t = blockIdx.x * 256 + tid;
        if (t >= A_TOTAL) return;
        const int W4 = Wc / 4;
        int w4 = t % W4;
        int h  = (t / W4) % Hc;
        int b  = t / (W4 * Hc);
        int w0 = w4 * 4;

        bool box0 = false, box1 = false, box2 = false, box3 = false;
#pragma unroll
        for (int f = 0; f < Fc; f++) {
            int h1 = __ldg(bbh1 + b * Fc + f);
            int h2 = __ldg(bbh2 + b * Fc + f);
            if (h >= h1 && h < h2) {
                int w1 = __ldg(bbw1 + b * Fc + f);
                int w2 = __ldg(bbw2 + b * Fc + f);
                box0 |= (w0 + 0 >= w1 && w0 + 0 < w2);
                box1 |= (w0 + 1 >= w1 && w0 + 1 < w2);
                box2 |= (w0 + 2 >= w1 && w0 + 2 < w2);
                box3 |= (w0 + 3 >= w1 && w0 + 3 < w2);
            }
        }
        int ub = __ldg(u + b);
        bool any = box0 | box1 | box2 | box3;
        long long base = (long long)h * Wc + w0;

        // pred_label (int -> float)
        {
            const int4 lb = __ldcs((const int4*)(label + (long long)b  * HWc + base));
            const int4 lu = any ? __ldcs((const int4*)(label + (long long)ub * HWc + base)) : lb;
            float4 v;
            v.x = (float)(box0 ? lu.x : lb.x);
            v.y = (float)(box1 ? lu.y : lb.y);
            v.z = (float)(box2 ? lu.z : lb.z);
            v.w = (float)(box3 ? lu.w : lb.w);
            __stcs((float4*)(out + OFF_LABEL + (long long)b * HWc + base), v);
        }
        // range_scan, 5 channels
#pragma unroll
        for (int c = 0; c < Cc; c++) {
            const float4 sb = __ldcs((const float4*)(scan + ((long long)b  * Cc + c) * HWc + base));
            const float4 su = any ? __ldcs((const float4*)(scan + ((long long)ub * Cc + c) * HWc + base)) : sb;
            float4 v;
            v.x = box0 ? su.x : sb.x;
            v.y = box1 ? su.y : sb.y;
            v.z = box2 ? su.z : sb.z;
            v.w = box3 ? su.w : sb.w;
            __stcs((float4*)(out + OFF_SCAN + ((long long)b * Cc + c) * HWc + base), v);
        }
        return;
    }

    // ----------------- Part B: coords + embed + valid (2 points / group) -----------
    __shared__ int s_u[Bc], s_inv[Bc];
    __shared__ int s_h1[Bc * Fc], s_h2[Bc * Fc], s_w1[Bc * Fc], s_w2[Bc * Fc];

    if (tid < Bc * Fc) {
        s_h1[tid] = bbh1[tid];
        s_h2[tid] = bbh2[tid];
        s_w1[tid] = bbw1[tid];
        s_w2[tid] = bbw2[tid];
    }
    if (tid < Bc) s_u[tid] = u[tid];
    __syncthreads();
    if (tid < Bc) s_inv[s_u[tid]] = tid;
    __syncthreads();

    const int grp = tid >> 3;            // 0..31
    const int l   = tid & 7;             // lane within group
    const long long base = (long long)(blockIdx.x - A_BLOCKS) * 64;
    const long long g0 = base + grp;          // point 0
    const long long g1 = base + 32 + grp;     // point 1

    // --- flags for both points ---
    int pb0 = __ldg(pc + g0 * 3 + 0);
    int pw0 = __ldg(pc + g0 * 3 + 1);
    int ph0 = __ldg(pc + g0 * 3 + 2);
    int pb1 = __ldg(pc + g1 * 3 + 0);
    int pw1 = __ldg(pc + g1 * 3 + 1);
    int ph1 = __ldg(pc + g1 * 3 + 2);
    int ic0 = s_inv[pb0];
    int ic1 = s_inv[pb1];

    bool own0  = box_eval(s_h1, s_h2, s_w1, s_w2, pb0, ph0, pw0);
    bool cut0  = box_eval(s_h1, s_h2, s_w1, s_w2, ic0, ph0, pw0);
    bool keep0 = !own0;
    bool own1  = box_eval(s_h1, s_h2, s_w1, s_w2, pb1, ph1, pw1);
    bool cut1  = box_eval(s_h1, s_h2, s_w1, s_w2, ic1, ph1, pw1);
    bool keep1 = !own1;

    // --- issue all 4 embed loads before any store (read burst, MLP=4) ---
    const float4 z = make_float4(0.f, 0.f, 0.f, 0.f);
    float4 a0 = z, a1 = z, c0 = z, c1 = z;
    const float4* s0 = (const float4*)(embed + g0 * 64);
    const float4* s1 = (const float4*)(embed + g1 * 64);
    bool ld0 = keep0 | cut0;
    bool ld1 = keep1 | cut1;
    if (ld0) { a0 = __ldcs(s0 + l); a1 = __ldcs(s0 + l + 8); }
    if (ld1) { c0 = __ldcs(s1 + l); c1 = __ldcs(s1 + l + 8); }

    // --- write burst: 8 STG.128 ---
    float4* o10 = (float4*)(out + OFF_EMBED + g0 * 64);
    float4* o20 = (float4*)(out + OFF_EMBED + ((long long)Nc + g0) * 64);
    float4* o11 = (float4*)(out + OFF_EMBED + g1 * 64);
    float4* o21 = (float4*)(out + OFF_EMBED + ((long long)Nc + g1) * 64);
    __stcs(o10 + l,     keep0 ? a0 : z);
    __stcs(o10 + l + 8, keep0 ? a1 : z);
    __stcs(o11 + l,     keep1 ? c0 : z);
    __stcs(o11 + l + 8, keep1 ? c1 : z);
    __stcs(o20 + l,     cut0 ? a0 : z);
    __stcs(o20 + l + 8, cut0 ? a1 : z);
    __stcs(o21 + l,     cut1 ? c0 : z);
    __stcs(o21 + l + 8, cut1 ? c1 : z);

    // --- coords + valid ---
    if (l == 0) {
        float* oc = out + OFF_COORD + g0 * 3;
        oc[0] = keep0 ? (float)pb0 : -1.f;
        oc[1] = keep0 ? (float)pw0 : -1.f;
        oc[2] = keep0 ? (float)ph0 : -1.f;
        out[OFF_VALID + g0] = keep0 ? 1.f : 0.f;
    } else if (l == 1) {
        float* oc = out + OFF_COORD + ((long long)Nc + g0) * 3;
        oc[0] = cut0 ? (float)ic0 : -1.f;
        oc[1] = cut0 ? (float)pw0 : -1.f;
        oc[2] = cut0 ? (float)ph0 : -1.f;
        out[OFF_VALID + (long long)Nc + g0] = cut0 ? 1.f : 0.f;
    } else if (l == 2) {
        float* oc = out + OFF_COORD + g1 * 3;
        oc[0] = keep1 ? (float)pb1 : -1.f;
        oc[1] = keep1 ? (float)pw1 : -1.f;
        oc[2] = keep1 ? (float)ph1 : -1.f;
        out[OFF_VALID + g1] = keep1 ? 1.f : 0.f;
    } else if (l == 3) {
        float* oc = out + OFF_COORD + ((long long)Nc + g1) * 3;
        oc[0] = cut1 ? (float)ic1 : -1.f;
        oc[1] = cut1 ? (float)pw1 : -1.f;
        oc[2] = cut1 ? (float)ph1 : -1.f;
        out[OFF_VALID + (long long)Nc + g1] = cut1 ? 1.f : 0.f;
    }
}

extern "C" void kernel_launch(void* const* d_in, const int* in_sizes, int n_in,
                              void* d_out, int out_size)
{
    const float* range_scan  = (const float*)d_in[0];
    const int*   pc          = (const int*)  d_in[1];
    const float* range_embed = (const float*)d_in[2];
    const int*   pred_label  = (const int*)  d_in[3];
    const int*   u_rand      = (const int*)  d_in[4];
    const int*   bbw1        = (const int*)  d_in[5];
    const int*   bbw2        = (const int*)  d_in[6];
    const int*   bbh1        = (const int*)  d_in[7];
    const int*   bbh2        = (const int*)  d_in[8];
    float* out = (float*)d_out;

    range_mix_fused_kernel<<<A_BLOCKS + B_BLOCKS, 256>>>(
        range_scan, pc, range_embed, pred_label, u_rand,
        bbw1, bbw2, bbh1, bbh2, out);
}

// round 5
// speedup vs baseline: 1.0507x; 1.0507x over previous
#include <cuda_runtime.h>
#include <cuda_bf16.h>

// Problem constants
#define Bc 8
#define Cc 5
#define Hc 64
#define Wc 2048
#define Nc 1048576
#define Dc 64
#define Fc 4
#define HWc (Hc * Wc)                  // 131072

// Output section offsets (float32 elements, reference tuple order)
#define OFF_SCAN   0LL
#define OFF_COORD  5242880LL           // B*C*H*W
#define OFF_LABEL  11534336LL          // + 2N*3
#define OFF_EMBED  12582912LL          // + B*H*W
#define OFF_VALID  146800640LL         // + 2N*D

// Grid split: B (points) blocks first, then A (scan/label) blocks.
#define B_BLOCKS  (Nc / 32)                // 32768 (32 points / 256-thr block)
#define A_TOTAL   (Bc * Hc * (Wc / 4))     // 131072 threads
#define A_BLOCKS  ((A_TOTAL + 255) / 256)  // 512

__device__ __forceinline__ bool box_eval(
    const int* s_h1, const int* s_h2, const int* s_w1, const int* s_w2,
    int b, int h, int w)
{
    bool r = false;
#pragma unroll
    for (int f = 0; f < Fc; f++) {
        int i = b * Fc + f;
        r |= (h >= s_h1[i]) & (h < s_h2[i]) & (w >= s_w1[i]) & (w < s_w2[i]);
    }
    return r;
}

__global__ __launch_bounds__(256) void range_mix_fused_kernel(
    const float* __restrict__ scan,
    const int*   __restrict__ pc,
    const float* __restrict__ embed,
    const int*   __restrict__ label,
    const int*   __restrict__ u,
    const int*   __restrict__ bbw1, const int* __restrict__ bbw2,
    const int*   __restrict__ bbh1, const int* __restrict__ bbh2,
    float*       __restrict__ out)
{
    const int tid = threadIdx.x;

    if (blockIdx.x >= B_BLOCKS) {
        // ----------------- Part A: mix_range_scan + mix_pred_label -----------------
        int t = (blockIdx.x - B_BLOCKS) * 256 + tid;
        if (t >= A_TOTAL) return;
        const int W4 = Wc / 4;
        int w4 = t % W4;
        int h  = (t / W4) % Hc;
        int b  = t / (W4 * Hc);
        int w0 = w4 * 4;

        bool box0 = false, box1 = false, box2 = false, box3 = false;
#pragma unroll
        for (int f = 0; f < Fc; f++) {
            int h1 = __ldg(bbh1 + b * Fc + f);
            int h2 = __ldg(bbh2 + b * Fc + f);
            if (h >= h1 && h < h2) {
                int w1 = __ldg(bbw1 + b * Fc + f);
                int w2 = __ldg(bbw2 + b * Fc + f);
                box0 |= (w0 + 0 >= w1 && w0 + 0 < w2);
                box1 |= (w0 + 1 >= w1 && w0 + 1 < w2);
                box2 |= (w0 + 2 >= w1 && w0 + 2 < w2);
                box3 |= (w0 + 3 >= w1 && w0 + 3 < w2);
            }
        }
        int ub = __ldg(u + b);
        bool any = box0 | box1 | box2 | box3;
        long long base = (long long)h * Wc + w0;

        // pred_label (int -> float)
        {
            const int4 lb = __ldcs((const int4*)(label + (long long)b  * HWc + base));
            const int4 lu = any ? __ldcs((const int4*)(label + (long long)ub * HWc + base)) : lb;
            float4 v;
            v.x = (float)(box0 ? lu.x : lb.x);
            v.y = (float)(box1 ? lu.y : lb.y);
            v.z = (float)(box2 ? lu.z : lb.z);
            v.w = (float)(box3 ? lu.w : lb.w);
            __stcs((float4*)(out + OFF_LABEL + (long long)b * HWc + base), v);
        }
        // range_scan, 5 channels
#pragma unroll
        for (int c = 0; c < Cc; c++) {
            const float4 sb = __ldcs((const float4*)(scan + ((long long)b  * Cc + c) * HWc + base));
            const float4 su = any ? __ldcs((const float4*)(scan + ((long long)ub * Cc + c) * HWc + base)) : sb;
            float4 v;
            v.x = box0 ? su.x : sb.x;
            v.y = box1 ? su.y : sb.y;
            v.z = box2 ? su.z : sb.z;
            v.w = box3 ? su.w : sb.w;
            __stcs((float4*)(out + OFF_SCAN + ((long long)b * Cc + c) * HWc + base), v);
        }
        return;
    }

    // ----------------- Part B: coords + embed + valid -----------------
    __shared__ int s_u[Bc], s_inv[Bc];
    __shared__ int s_h1[Bc * Fc], s_h2[Bc * Fc], s_w1[Bc * Fc], s_w2[Bc * Fc];
    __shared__ float s_c1[96], s_c2[96];     // keep/cut coords for 32 points
    __shared__ float s_v[64];                // valid keep[32] | cut[32]

    if (tid < Bc * Fc) {
        s_h1[tid] = bbh1[tid];
        s_h2[tid] = bbh2[tid];
        s_w1[tid] = bbw1[tid];
        s_w2[tid] = bbw2[tid];
    }
    if (tid < Bc) s_u[tid] = u[tid];
    __syncthreads();
    if (tid < Bc) s_inv[s_u[tid]] = tid;
    __syncthreads();

    const int grp = tid >> 3;                        // 0..31 point-in-block
    const int l   = tid & 7;                         // lane within group
    const long long base = (long long)blockIdx.x * 32;
    const long long g = base + grp;                  // point id

    int pb = __ldg(pc + g * 3 + 0);
    int pw = __ldg(pc + g * 3 + 1);
    int ph = __ldg(pc + g * 3 + 2);
    int icut = s_inv[pb];

    bool own  = box_eval(s_h1, s_h2, s_w1, s_w2, pb,   ph, pw);
    bool cut  = box_eval(s_h1, s_h2, s_w1, s_w2, icut, ph, pw);
    bool keep = !own;

    // embed row: lane l covers float4 #l and #(l+8) (contiguous 128B halves)
    const float4 z = make_float4(0.f, 0.f, 0.f, 0.f);
    float4 v0 = z, v1 = z;
    if (keep | cut) {
        const float4* src = (const float4*)(embed + g * 64);
        v0 = __ldcs(src + l);
        v1 = __ldcs(src + l + 8);
    }
    float4* o1 = (float4*)(out + OFF_EMBED + g * 64);
    float4* o2 = (float4*)(out + OFF_EMBED + ((long long)Nc + g) * 64);
    __stcs(o1 + l,     keep ? v0 : z);
    __stcs(o1 + l + 8, keep ? v1 : z);
    __stcs(o2 + l,     cut  ? v0 : z);
    __stcs(o2 + l + 8, cut  ? v1 : z);

    // stage coords + valid in SMEM (dense flush below)
    if (l == 0) {
        s_c1[grp * 3 + 0] = keep ? (float)pb : -1.f;
        s_c1[grp * 3 + 1] = keep ? (float)pw : -1.f;
        s_c1[grp * 3 + 2] = keep ? (float)ph : -1.f;
        s_v[grp] = keep ? 1.f : 0.f;
    } else if (l == 1) {
        s_c2[grp * 3 + 0] = cut ? (float)icut : -1.f;
        s_c2[grp * 3 + 1] = cut ? (float)pw   : -1.f;
        s_c2[grp * 3 + 2] = cut ? (float)ph   : -1.f;
        s_v[32 + grp] = cut ? 1.f : 0.f;
    }
    __syncthreads();

    // dense float4 flush: 24 + 24 + 8 + 8 = 64 threads
    if (tid < 24) {
        ((float4*)(out + OFF_COORD + base * 3))[tid] = ((const float4*)s_c1)[tid];
    } else if (tid < 48) {
        int i = tid - 24;
        ((float4*)(out + OFF_COORD + ((long long)Nc + base) * 3))[i] = ((const float4*)s_c2)[i];
    } else if (tid < 56) {
        int i = tid - 48;
        ((float4*)(out + OFF_VALID + base))[i] = ((const float4*)s_v)[i];
    } else if (tid < 64) {
        int i = tid - 56;
        ((float4*)(out + OFF_VALID + (long long)Nc + base))[i] = ((const float4*)(s_v + 32))[i];
    }
}

extern "C" void kernel_launch(void* const* d_in, const int* in_sizes, int n_in,
                              void* d_out, int out_size)
{
    const float* range_scan  = (const float*)d_in[0];
    const int*   pc          = (const int*)  d_in[1];
    const float* range_embed = (const float*)d_in[2];
    const int*   pred_label  = (const int*)  d_in[3];
    const int*   u_rand      = (const int*)  d_in[4];
    const int*   bbw1        = (const int*)  d_in[5];
    const int*   bbw2        = (const int*)  d_in[6];
    const int*   bbh1        = (const int*)  d_in[7];
    const int*   bbh2        = (const int*)  d_in[8];
    float* out = (float*)d_out;

    range_mix_fused_kernel<<<B_BLOCKS + A_BLOCKS, 256>>>(
        range_scan, pc, range_embed, pred_label, u_rand,
        bbw1, bbw2, bbh1, bbh2, out);
}

// round 7
// speedup vs baseline: 1.0946x; 1.0417x over previous
#include <cuda_runtime.h>
#include <cuda_bf16.h>

// Problem constants
#define Bc 8
#define Cc 5
#define Hc 64
#define Wc 2048
#define Nc 1048576
#define Dc 64
#define Fc 4
#define HWc (Hc * Wc)                  // 131072

// Output section offsets (float32 elements, reference tuple order)
#define OFF_SCAN   0LL
#define OFF_COORD  5242880LL           // B*C*H*W
#define OFF_LABEL  11534336LL          // + 2N*3
#define OFF_EMBED  12582912LL          // + B*H*W
#define OFF_VALID  146800640LL         // + 2N*D

// Grid split: A (scan/label) blocks first, then B (points) blocks.
#define A_TOTAL   (Bc * Hc * (Wc / 4))     // 131072 threads
#define A_BLOCKS  ((A_TOTAL + 255) / 256)  // 512
#define B_BLOCKS  (Nc / 32)                // 32768 (32 points / 256-thr block)

__device__ __forceinline__ bool box_eval(
    const int* s_h1, const int* s_h2, const int* s_w1, const int* s_w2,
    int b, int h, int w)
{
    bool r = false;
#pragma unroll
    for (int f = 0; f < Fc; f++) {
        int i = b * Fc + f;
        r |= (h >= s_h1[i]) & (h < s_h2[i]) & (w >= s_w1[i]) & (w < s_w2[i]);
    }
    return r;
}

__global__ __launch_bounds__(256) void range_mix_fused_kernel(
    const float* __restrict__ scan,
    const int*   __restrict__ pc,
    const float* __restrict__ embed,
    const int*   __restrict__ label,
    const int*   __restrict__ u,
    const int*   __restrict__ bbw1, const int* __restrict__ bbw2,
    const int*   __restrict__ bbh1, const int* __restrict__ bbh2,
    float*       __restrict__ out)
{
    const int tid = threadIdx.x;

    if (blockIdx.x < A_BLOCKS) {
        // ----------------- Part A: mix_range_scan + mix_pred_label -----------------
        int t = blockIdx.x * 256 + tid;
        if (t >= A_TOTAL) return;
        const int W4 = Wc / 4;
        int w4 = t % W4;
        int h  = (t / W4) % Hc;
        int b  = t / (W4 * Hc);
        int w0 = w4 * 4;

        bool box0 = false, box1 = false, box2 = false, box3 = false;
#pragma unroll
        for (int f = 0; f < Fc; f++) {
            int h1 = __ldg(bbh1 + b * Fc + f);
            int h2 = __ldg(bbh2 + b * Fc + f);
            if (h >= h1 && h < h2) {
                int w1 = __ldg(bbw1 + b * Fc + f);
                int w2 = __ldg(bbw2 + b * Fc + f);
                box0 |= (w0 + 0 >= w1 && w0 + 0 < w2);
                box1 |= (w0 + 1 >= w1 && w0 + 1 < w2);
                box2 |= (w0 + 2 >= w1 && w0 + 2 < w2);
                box3 |= (w0 + 3 >= w1 && w0 + 3 < w2);
            }
        }
        int ub = __ldg(u + b);
        bool any = box0 | box1 | box2 | box3;
        long long base = (long long)h * Wc + w0;

        // pred_label (int -> float)
        {
            const int4 lb = __ldcs((const int4*)(label + (long long)b  * HWc + base));
            const int4 lu = any ? __ldcs((const int4*)(label + (long long)ub * HWc + base)) : lb;
            float4 v;
            v.x = (float)(box0 ? lu.x : lb.x);
            v.y = (float)(box1 ? lu.y : lb.y);
            v.z = (float)(box2 ? lu.z : lb.z);
            v.w = (float)(box3 ? lu.w : lb.w);
            __stcs((float4*)(out + OFF_LABEL + (long long)b * HWc + base), v);
        }
        // range_scan, 5 channels
#pragma unroll
        for (int c = 0; c < Cc; c++) {
            const float4 sb = __ldcs((const float4*)(scan + ((long long)b  * Cc + c) * HWc + base));
            const float4 su = any ? __ldcs((const float4*)(scan + ((long long)ub * Cc + c) * HWc + base)) : sb;
            float4 v;
            v.x = box0 ? su.x : sb.x;
            v.y = box1 ? su.y : sb.y;
            v.z = box2 ? su.z : sb.z;
            v.w = box3 ? su.w : sb.w;
            __stcs((float4*)(out + OFF_SCAN + ((long long)b * Cc + c) * HWc + base), v);
        }
        return;
    }

    // ----------------- Part B: coords + embed + valid -----------------
    __shared__ int s_u[Bc], s_inv[Bc];
    __shared__ int s_h1[Bc * Fc], s_h2[Bc * Fc], s_w1[Bc * Fc], s_w2[Bc * Fc];
    // Per-warp staging: [0:12) keep coords, [12:16) valid keep,
    //                   [16:28) cut coords, [28:32) valid cut
    __shared__ __align__(16) float s_st[8][32];

    if (tid < Bc * Fc) {
        s_h1[tid] = bbh1[tid];
        s_h2[tid] = bbh2[tid];
        s_w1[tid] = bbw1[tid];
        s_w2[tid] = bbw2[tid];
    }
    if (tid < Bc) s_u[tid] = u[tid];
    __syncthreads();
    if (tid < Bc) s_inv[s_u[tid]] = tid;
    __syncthreads();

    const int grp  = tid >> 3;           // 0..31 point-in-block
    const int l    = tid & 7;            // lane within group
    const int w    = tid >> 5;           // warp id 0..7
    const int grp2 = grp & 3;            // point-in-warp 0..3
    const long long base = (long long)(blockIdx.x - A_BLOCKS) * 32;
    const long long g = base + grp;      // point id

    int pb = __ldg(pc + g * 3 + 0);
    int pw = __ldg(pc + g * 3 + 1);
    int ph = __ldg(pc + g * 3 + 2);
    int icut = s_inv[pb];

    bool own  = box_eval(s_h1, s_h2, s_w1, s_w2, pb,   ph, pw);
    bool cut  = box_eval(s_h1, s_h2, s_w1, s_w2, icut, ph, pw);
    bool keep = !own;

    // stage coords + valid into warp-local SMEM (dense flush below)
    if (l == 0) {
        s_st[w][grp2 * 3 + 0] = keep ? (float)pb : -1.f;
        s_st[w][grp2 * 3 + 1] = keep ? (float)pw : -1.f;
        s_st[w][grp2 * 3 + 2] = keep ? (float)ph : -1.f;
        s_st[w][12 + grp2]    = keep ? 1.f : 0.f;
    } else if (l == 1) {
        s_st[w][16 + grp2 * 3 + 0] = cut ? (float)icut : -1.f;
        s_st[w][16 + grp2 * 3 + 1] = cut ? (float)pw   : -1.f;
        s_st[w][16 + grp2 * 3 + 2] = cut ? (float)ph   : -1.f;
        s_st[w][28 + grp2]         = cut ? 1.f : 0.f;
    }

    // embed row: lane l covers float4 #l and #(l+8) (contiguous 128B halves)
    const float4 z = make_float4(0.f, 0.f, 0.f, 0.f);
    float4 v0 = z, v1 = z;
    if (keep | cut) {
        const float4* src = (const float4*)(embed + g * 64);
        v0 = __ldcs(src + l);
        v1 = __ldcs(src + l + 8);
    }
    float4* o1 = (float4*)(out + OFF_EMBED + g * 64);
    float4* o2 = (float4*)(out + OFF_EMBED + ((long long)Nc + g) * 64);
    __stcs(o1 + l,     keep ? v0 : z);
    __stcs(o1 + l + 8, keep ? v1 : z);
    __stcs(o2 + l,     cut  ? v0 : z);
    __stcs(o2 + l + 8, cut  ? v1 : z);

    __syncwarp();

    // dense per-warp flush: warp covers points g0..g0+3
    const long long g0 = base + w * 4;
    const int lane = tid & 31;
    const float4* st4 = (const float4*)&s_st[w][0];
    if (lane < 3) {
        // keep coords: 12 floats = 3 float4
        ((float4*)(out + OFF_COORD + g0 * 3))[lane] = st4[lane];
    } else if (lane == 3) {
        // valid keep: 4 floats
        *((float4*)(out + OFF_VALID + g0)) = st4[3];
    } else if (lane < 7) {
        // cut coords
        ((float4*)(out + OFF_COORD + ((long long)Nc + g0) * 3))[lane - 4] = st4[lane];
    } else if (lane == 7) {
        // valid cut
        *((float4*)(out + OFF_VALID + (long long)Nc + g0)) = st4[7];
    }
}

extern "C" void kernel_launch(void* const* d_in, const int* in_sizes, int n_in,
                              void* d_out, int out_size)
{
    const float* range_scan  = (const float*)d_in[0];
    const int*   pc          = (const int*)  d_in[1];
    const float* range_embed = (const float*)d_in[2];
    const int*   pred_label  = (const int*)  d_in[3];
    const int*   u_rand      = (const int*)  d_in[4];
    const int*   bbw1        = (const int*)  d_in[5];
    const int*   bbw2        = (const int*)  d_in[6];
    const int*   bbh1        = (const int*)  d_in[7];
    const int*   bbh2        = (const int*)  d_in[8];
    float* out = (float*)d_out;

    range_mix_fused_kernel<<<A_BLOCKS + B_BLOCKS, 256>>>(
        range_scan, pc, range_embed, pred_label, u_rand,
        bbw1, bbw2, bbh1, bbh2, out);
}